// round 4
// baseline (speedup 1.0000x reference)
#include <cuda_runtime.h>

#define Nn   1024
#define Cc   64
#define HID  128
#define TS   16                          // output unit edge
#define NTS  (Nn / TS)                   // 64
#define NUNITS (NTS * (NTS + 1) / 2)     // 2080
#define HCH  64                          // h chunk in shared

// interleaved: g_p[h*Nn + n] = (pi[h,n], pj[h,n])
__device__ float2 g_p[HID * Nn];

__device__ __forceinline__ float tanh_apx(float x) {
    float y;
    asm("tanh.approx.f32 %0, %1;" : "=f"(y) : "f"(x));
    return y;
}

// ---------------------------------------------------------------------------
// prep: pi[h,n] = sum_c W1[h,Cc+c]*tanh(x[c,n]) + b1[h]
//       pj[h,n] = sum_c W1[h,   c]*tanh(x[c,n])
// grid 256 x 128 threads, block = 4-column n chunk, thread = one h
// ---------------------------------------------------------------------------
#define NCH 4
__global__ void prep_kernel(const float* __restrict__ x,
                            const float* __restrict__ W1,
                            const float* __restrict__ b1) {
    __shared__ float t_s[Cc][NCH];
    const int n0  = blockIdx.x * NCH;
    const int tid = threadIdx.x;

    for (int k = tid; k < Cc * NCH; k += 128) {
        int c = k / NCH, n = k % NCH;
        t_s[c][n] = tanhf(x[c * Nn + n0 + n]);   // precise tanh in pre-pass
    }
    __syncthreads();

    const int h = tid;
    float accj[NCH], acci[NCH];
    const float bb = b1[h];
#pragma unroll
    for (int n = 0; n < NCH; n++) { accj[n] = 0.0f; acci[n] = bb; }

#pragma unroll
    for (int c = 0; c < Cc; c++) {
        float wj = W1[h * (2 * Cc) + c];
        float wi = W1[h * (2 * Cc) + Cc + c];
#pragma unroll
        for (int n = 0; n < NCH; n++) {
            float t = t_s[c][n];
            accj[n] = fmaf(wj, t, accj[n]);
            acci[n] = fmaf(wi, t, acci[n]);
        }
    }
#pragma unroll
    for (int n = 0; n < NCH; n++)
        g_p[h * Nn + n0 + n] = make_float2(acci[n], accj[n]);
}

// ---------------------------------------------------------------------------
// pair: triangular unit (a <= b): i in [16a,16a+16), j in [16b,16b+16).
// 64 threads, each owns a 2x2 (i,j) patch:
//   acc[A][B] = sum_h w2[h]*( tanh(pi[h,iA]+pj[h,jB]) + tanh(pi[h,jB]+pj[h,iA]) )
//   out[iA,jB] = out[jB,iA] = acc[A][B] + 2*b2
// ---------------------------------------------------------------------------
__global__ __launch_bounds__(64) void pair_kernel(const float* __restrict__ W2,
                                                  const float* __restrict__ b2,
                                                  float* __restrict__ out) {
    __shared__ __align__(16) float2 pS[HCH][2 * TS];  // [h][0..15]=i cols, [16..31]=j cols
    __shared__ float w2s[HID];

    // triangular decode
    int rem = blockIdx.x, a = 0, len = NTS;
    while (rem >= len) { rem -= len; a++; len--; }
    const int b  = a + rem;
    const int i0 = a * TS, j0 = b * TS;

    const int tid = threadIdx.x;
    for (int t = tid; t < HID; t += 64) w2s[t] = W2[t];

    const int ii2 = tid >> 3;        // 0..7  -> i pair
    const int jj2 = tid & 7;         // 0..7  -> j pair

    float acc00 = 0.f, acc01 = 0.f, acc10 = 0.f, acc11 = 0.f;

    for (int hc = 0; hc < HID / HCH; hc++) {
        __syncthreads();
        // stage HCH h-rows x 32 float2 cols (16 i-side + 16 j-side) = 1024 float4
        for (int t = tid; t < HCH * 16; t += 64) {
            int h    = t >> 4;
            int q    = t & 15;
            int side = q >> 3;             // 0 = i-side, 1 = j-side
            int c2   = (q & 7) * 2;        // float2 column within side
            int hg   = hc * HCH + h;
            int base = side ? j0 : i0;
            float4 v = *(const float4*)&g_p[hg * Nn + base + c2];
            *(float4*)&pS[h][side * TS + c2] = v;
        }
        __syncthreads();

#pragma unroll 8
        for (int h = 0; h < HCH; h++) {
            // (pi_i0, pj_i0, pi_i1, pj_i1)
            float4 ai = *(const float4*)&pS[h][ii2 * 2];
            // (pi_j0, pj_j0, pi_j1, pj_j1)
            float4 aj = *(const float4*)&pS[h][TS + jj2 * 2];
            float  w  = w2s[hc * HCH + h];

            acc00 = fmaf(w, tanh_apx(ai.x + aj.y) + tanh_apx(aj.x + ai.y), acc00);
            acc01 = fmaf(w, tanh_apx(ai.x + aj.w) + tanh_apx(aj.z + ai.y), acc01);
            acc10 = fmaf(w, tanh_apx(ai.z + aj.y) + tanh_apx(aj.x + ai.w), acc10);
            acc11 = fmaf(w, tanh_apx(ai.z + aj.w) + tanh_apx(aj.z + ai.w), acc11);
        }
    }

    const float bb2 = 2.0f * b2[0];
    const int gi = i0 + ii2 * 2;
    const int gj = j0 + jj2 * 2;

    float v00 = acc00 + bb2, v01 = acc01 + bb2;
    float v10 = acc10 + bb2, v11 = acc11 + bb2;

    // upper tile (two float2 row segments)
    *(float2*)&out[(gi + 0) * Nn + gj] = make_float2(v00, v01);
    *(float2*)&out[(gi + 1) * Nn + gj] = make_float2(v10, v11);
    // mirrored lower tile
    *(float2*)&out[(gj + 0) * Nn + gi] = make_float2(v00, v10);
    *(float2*)&out[(gj + 1) * Nn + gi] = make_float2(v01, v11);
}

extern "C" void kernel_launch(void* const* d_in, const int* in_sizes, int n_in,
                              void* d_out, int out_size) {
    const float* x  = (const float*)d_in[0];
    const float* W1 = (const float*)d_in[1];
    const float* b1 = (const float*)d_in[2];
    const float* W2 = (const float*)d_in[3];
    const float* b2 = (const float*)d_in[4];
    float* out = (float*)d_out;

    prep_kernel<<<Nn / NCH, 128>>>(x, W1, b1);
    pair_kernel<<<NUNITS, 64>>>(W2, b2, out);
}